// round 8
// baseline (speedup 1.0000x reference)
#include <cuda_runtime.h>
#include <cstdint>

// out = (x != corner_of_plane) ? 1.0f : 0.0f
// x: (16, 3, 1024, 1024) fp32, plane = 1<<20 elements (262144 float4s).
//
// Pure HBM streamer at the measured mixed R/W ceiling (~6.28 TB/s on this
// GB300). Measured-best configuration across 7 probed variants:
//   - 256 threads x UNROLL 4 (64 B/thread), 12288 CTAs (exact fit)
//   - __ldcs reads (evict-first, zero reuse)
//   - __stcs stores (beats .wb and .wt by 1.5-2 us in steady-state replay)
//   - one cached corner load per block-tile (tile always within one plane)
//   - 32-bit indexing (n4 = 12582912 < 2^31): single-IMAD address math.

#define THREADS 256
#define UNROLL 4
#define TILE_F4 (THREADS * UNROLL)   // 1024 float4s per block

__global__ void __launch_bounds__(THREADS) remover_kernel(
    const float* __restrict__ x,
    float* __restrict__ out) {

    const float4* __restrict__ x4 = reinterpret_cast<const float4*>(x);
    float4* __restrict__ out4 = reinterpret_cast<float4*>(out);

    unsigned tile_base = blockIdx.x * TILE_F4;      // float4 index, < 2^24
    unsigned base = tile_base + threadIdx.x;

    // plane = element_idx >> 20 = float4_idx >> 18 — uniform across the block
    // (tile of 1024 float4s never crosses a 262144-float4 plane boundary).
    unsigned plane = tile_base >> 18;
    float corner = __ldg(x + ((size_t)plane << 20));

    float4 v[UNROLL];
#pragma unroll
    for (int u = 0; u < UNROLL; u++) {
        v[u] = __ldcs(x4 + base + u * THREADS);
    }

#pragma unroll
    for (int u = 0; u < UNROLL; u++) {
        float4 r;
        r.x = (v[u].x != corner) ? 1.0f : 0.0f;
        r.y = (v[u].y != corner) ? 1.0f : 0.0f;
        r.z = (v[u].z != corner) ? 1.0f : 0.0f;
        r.w = (v[u].w != corner) ? 1.0f : 0.0f;
        __stcs(out4 + base + u * THREADS, r);
    }
}

extern "C" void kernel_launch(void* const* d_in, const int* in_sizes, int n_in,
                              void* d_out, int out_size) {
    const float* x = (const float*)d_in[0];
    float* out = (float*)d_out;

    long long n = (long long)in_sizes[0];            // 50331648
    long long n4 = n >> 2;                           // 12582912 float4s
    long long blocks = (n4 + TILE_F4 - 1) / TILE_F4; // 12288, exact fit

    remover_kernel<<<(unsigned)blocks, THREADS>>>(x, out);
}

// round 9
// speedup vs baseline: 1.0227x; 1.0227x over previous
#include <cuda_runtime.h>
#include <cstdint>

// out = (x != corner_of_plane) ? 1.0f : 0.0f
// x: (16, 3, 1024, 1024) fp32, plane = 1<<20 elements.
//
// FINAL: pure HBM streamer at the measured mixed read/write DRAM ceiling
// (~6.28 TB/s on this GB300; 384 MB irreducible traffic -> ~61 us floor).
// Measured-best configuration across 8 probed variants:
//   - 256 threads x UNROLL 4 (64 B/thread), 12288 CTAs, exact fit, no bounds
//   - __ldcs reads (evict-first; zero reuse)
//   - __stcs stores (measured best vs .wb / .wt in steady-state graph replay)
//   - one L1/L2-cached corner load per thread (block tile of 4096 elements
//     always lies within a single 2^20-element plane)

#define THREADS 256
#define UNROLL 4

__global__ void __launch_bounds__(THREADS) remover_kernel(
    const float* __restrict__ x,
    float* __restrict__ out) {

    const float4* __restrict__ x4 = reinterpret_cast<const float4*>(x);
    float4* __restrict__ out4 = reinterpret_cast<float4*>(out);

    // float4-index base for this thread's first vector
    long long base = (long long)blockIdx.x * (THREADS * UNROLL) + threadIdx.x;

    // element plane = (float4_idx * 4) >> 20 = float4_idx >> 18.
    // Tile spans float4 indices [blk*1024, blk*1024+1024) -> one plane.
    long long plane = base >> 18;
    float corner = __ldg(x + (plane << 20));

    // Front-batched independent loads (MLP ~ 4-5 per thread)
    float4 v0 = __ldcs(x4 + base);
    float4 v1 = __ldcs(x4 + base + THREADS);
    float4 v2 = __ldcs(x4 + base + 2 * THREADS);
    float4 v3 = __ldcs(x4 + base + 3 * THREADS);

    float4 r0, r1, r2, r3;
    r0.x = (v0.x != corner) ? 1.0f : 0.0f;
    r0.y = (v0.y != corner) ? 1.0f : 0.0f;
    r0.z = (v0.z != corner) ? 1.0f : 0.0f;
    r0.w = (v0.w != corner) ? 1.0f : 0.0f;
    r1.x = (v1.x != corner) ? 1.0f : 0.0f;
    r1.y = (v1.y != corner) ? 1.0f : 0.0f;
    r1.z = (v1.z != corner) ? 1.0f : 0.0f;
    r1.w = (v1.w != corner) ? 1.0f : 0.0f;
    r2.x = (v2.x != corner) ? 1.0f : 0.0f;
    r2.y = (v2.y != corner) ? 1.0f : 0.0f;
    r2.z = (v2.z != corner) ? 1.0f : 0.0f;
    r2.w = (v2.w != corner) ? 1.0f : 0.0f;
    r3.x = (v3.x != corner) ? 1.0f : 0.0f;
    r3.y = (v3.y != corner) ? 1.0f : 0.0f;
    r3.z = (v3.z != corner) ? 1.0f : 0.0f;
    r3.w = (v3.w != corner) ? 1.0f : 0.0f;

    __stcs(out4 + base, r0);
    __stcs(out4 + base + THREADS, r1);
    __stcs(out4 + base + 2 * THREADS, r2);
    __stcs(out4 + base + 3 * THREADS, r3);
}

extern "C" void kernel_launch(void* const* d_in, const int* in_sizes, int n_in,
                              void* d_out, int out_size) {
    const float* x = (const float*)d_in[0];
    float* out = (float*)d_out;

    long long n = (long long)in_sizes[0];        // 50331648
    long long n4 = n >> 2;                       // 12582912 float4s
    long long per_block = (long long)THREADS * UNROLL;  // 1024 float4s
    long long blocks = (n4 + per_block - 1) / per_block; // 12288, exact fit

    remover_kernel<<<(unsigned)blocks, THREADS>>>(x, out);
}